// round 2
// baseline (speedup 1.0000x reference)
#include <cuda_runtime.h>
#include <cuda_bf16.h>
#include <math.h>

// ---------------- problem constants ----------------
#define BATCH 48
#define HH 49
#define WW2 49
#define CC 128
#define LL (HH * WW2)            // 2401
#define NHEAD 4
#define HD 32
#define WS 7
#define SS 3
#define NWIN 49                  // (49/7)^2
#define NTOK 49                  // WS*WS
#define MTOT (BATCH * LL)        // 115248  (== BATCH*NWIN*NTOK)
#define HID 512

// ---------------- scratch (device globals; no allocations) ----------------
__device__ float g_xw[(size_t)MTOT * CC];      // LN1 + shifted windows; reused as proj out
__device__ float g_qkv[(size_t)MTOT * 3 * CC];
__device__ float g_attnout[(size_t)MTOT * CC];
__device__ float g_x2[(size_t)MTOT * CC];
__device__ float g_ln2[(size_t)MTOT * CC];
__device__ float g_h1[(size_t)MTOT * HID];

// ---------------- LN1 + cyclic shift + window partition ----------------
__global__ void ln1_shift_window_kernel(const float* __restrict__ x,
                                        const float* __restrict__ gw,
                                        const float* __restrict__ gb,
                                        float* __restrict__ xw) {
    int gid = blockIdx.x;               // 0 .. MTOT-1 : (b, window, token)
    int b   = gid / (NWIN * NTOK);
    int r   = gid % (NWIN * NTOK);
    int w   = r / NTOK;
    int n   = r % NTOK;
    int wh = w / 7, ww = w % 7, ti = n / 7, tj = n % 7;
    int i = wh * 7 + ti, j = ww * 7 + tj;           // shifted coords
    int si = (i + SS) % HH, sj = (j + SS) % WW2;    // source coords in x
    const float* src = x + ((size_t)b * LL + (size_t)si * WW2 + sj) * CC;

    int c = threadIdx.x;                 // 128 threads
    float v = src[c];
    float s = v, s2 = v * v;
    #pragma unroll
    for (int o = 16; o; o >>= 1) {
        s  += __shfl_xor_sync(0xFFFFFFFFu, s,  o);
        s2 += __shfl_xor_sync(0xFFFFFFFFu, s2, o);
    }
    __shared__ float sh[8];
    int warp = c >> 5, lane = c & 31;
    if (lane == 0) { sh[warp] = s; sh[warp + 4] = s2; }
    __syncthreads();
    s  = sh[0] + sh[1] + sh[2] + sh[3];
    s2 = sh[4] + sh[5] + sh[6] + sh[7];
    float mean = s * (1.0f / CC);
    float var  = s2 * (1.0f / CC) - mean * mean;
    float rstd = rsqrtf(var + 1e-5f);
    xw[(size_t)gid * CC + c] = (v - mean) * rstd * gw[c] + gb[c];
}

// ---------------- LN2 (plain row LN) ----------------
__global__ void ln2_kernel(const float* __restrict__ x2,
                           const float* __restrict__ gw,
                           const float* __restrict__ gb,
                           float* __restrict__ out) {
    int gid = blockIdx.x;
    const float* src = x2 + (size_t)gid * CC;
    int c = threadIdx.x;
    float v = src[c];
    float s = v, s2 = v * v;
    #pragma unroll
    for (int o = 16; o; o >>= 1) {
        s  += __shfl_xor_sync(0xFFFFFFFFu, s,  o);
        s2 += __shfl_xor_sync(0xFFFFFFFFu, s2, o);
    }
    __shared__ float sh[8];
    int warp = c >> 5, lane = c & 31;
    if (lane == 0) { sh[warp] = s; sh[warp + 4] = s2; }
    __syncthreads();
    s  = sh[0] + sh[1] + sh[2] + sh[3];
    s2 = sh[4] + sh[5] + sh[6] + sh[7];
    float mean = s * (1.0f / CC);
    float var  = s2 * (1.0f / CC) - mean * mean;
    float rstd = rsqrtf(var + 1e-5f);
    out[(size_t)gid * CC + c] = (v - mean) * rstd * gw[c] + gb[c];
}

// ---------------- fused window attention: QK^T + bias + mask + softmax + PV ----------------
__device__ __forceinline__ int region1d(int p) {
    // slices: [0,42) -> 0, [42,46) -> 1, [46,49) -> 2
    return (p < HH - WS) ? 0 : ((p < HH - SS) ? 1 : 2);
}

__global__ void attn_kernel(const float* __restrict__ qkv,
                            const float* __restrict__ rpb,
                            float* __restrict__ out) {
    int bw = blockIdx.x;                 // 0..2351
    int h  = blockIdx.y;                 // 0..3
    int w  = bw % NWIN;                  // window index

    __shared__ float sq[NTOK * HD];
    __shared__ float sk[NTOK * HD];
    __shared__ float sv[NTOK * HD];
    __shared__ float ss[NTOK * NTOK];

    int tid = threadIdx.x;               // 256 threads
    const float scale = 0.17677669529663687f;   // 32^-0.5
    size_t base = (size_t)bw * NTOK * (3 * CC);

    for (int i = tid; i < NTOK * HD; i += 256) {
        int n = i >> 5, d = i & 31;
        const float* row = qkv + base + (size_t)n * (3 * CC) + h * HD + d;
        sq[i] = row[0] * scale;
        sk[i] = row[CC];
        sv[i] = row[2 * CC];
    }
    __syncthreads();

    int wh = w / 7, wwc = w % 7;
    for (int idx = tid; idx < NTOK * NTOK; idx += 256) {
        int n = idx / NTOK, m = idx % NTOK;
        float acc = 0.f;
        #pragma unroll
        for (int d = 0; d < HD; d++) acc += sq[n * HD + d] * sk[m * HD + d];
        // relative position bias
        int ni = n / 7, nj = n % 7, mi = m / 7, mj = m % 7;
        int rel = (ni - mi + WS - 1) * (2 * WS - 1) + (nj - mj + WS - 1);
        acc += rpb[rel * NHEAD + h];
        // shift mask: am[w, n, m] = (mw[w,m] != mw[n,m]) ? -100 : 0
        int h1 = wh * 7 + mi, w1 = wwc * 7 + mj;
        int h2 = (n / 7) * 7 + mi, w2 = (n % 7) * 7 + mj;
        int r1 = 3 * region1d(h1) + region1d(w1);
        int r2 = 3 * region1d(h2) + region1d(w2);
        if (r1 != r2) acc -= 100.0f;
        ss[idx] = acc;
    }
    __syncthreads();

    // softmax: one row per warp (8 warps loop over 49 rows)
    int warp = tid >> 5, lane = tid & 31;
    for (int n = warp; n < NTOK; n += 8) {
        float v0 = ss[n * NTOK + lane];
        float v1 = (lane + 32 < NTOK) ? ss[n * NTOK + lane + 32] : -1e30f;
        float mx = fmaxf(v0, v1);
        #pragma unroll
        for (int o = 16; o; o >>= 1) mx = fmaxf(mx, __shfl_xor_sync(0xFFFFFFFFu, mx, o));
        float e0 = __expf(v0 - mx);
        float e1 = (lane + 32 < NTOK) ? __expf(v1 - mx) : 0.f;
        float sum = e0 + e1;
        #pragma unroll
        for (int o = 16; o; o >>= 1) sum += __shfl_xor_sync(0xFFFFFFFFu, sum, o);
        float inv = 1.0f / sum;
        ss[n * NTOK + lane] = e0 * inv;
        if (lane + 32 < NTOK) ss[n * NTOK + lane + 32] = e1 * inv;
    }
    __syncthreads();

    for (int i = tid; i < NTOK * HD; i += 256) {
        int n = i >> 5, d = i & 31;
        float acc = 0.f;
        #pragma unroll
        for (int m = 0; m < NTOK; m++) acc += ss[n * NTOK + m] * sv[m * HD + d];
        out[((size_t)bw * NTOK + n) * CC + h * HD + d] = acc;
    }
}

// ---------------- tiled fp32 GEMM: C[M,N] = A[M,K] @ Bw[N,K]^T + bias, epilogue ----------------
// EPI: 0 = none, 1 = exact GELU, 2 = += res[m*N+n]
template <int EPI>
__global__ void gemm64_kernel(const float* __restrict__ A,
                              const float* __restrict__ Bw,
                              const float* __restrict__ bias,
                              float* __restrict__ C,
                              int M, int N, int K,
                              const float* __restrict__ res) {
    __shared__ float As[16][64];
    __shared__ float Bs[16][64];
    int tid = threadIdx.x;             // 256
    int tx = tid & 15, ty = tid >> 4;
    int m0 = blockIdx.x * 64, n0 = blockIdx.y * 64;

    float acc[4][4] = {};
    int lrow = tid >> 2;               // 0..63
    int lcol = (tid & 3) * 4;          // 0,4,8,12
    const float* Aptr = A  + (size_t)(m0 + lrow) * K + lcol;
    const float* Bptr = Bw + (size_t)(n0 + lrow) * K + lcol;
    bool avalid = (m0 + lrow) < M;

    for (int k0 = 0; k0 < K; k0 += 16) {
        float4 av = avalid ? *(const float4*)(Aptr + k0) : make_float4(0.f, 0.f, 0.f, 0.f);
        float4 bv = *(const float4*)(Bptr + k0);
        As[lcol + 0][lrow] = av.x; As[lcol + 1][lrow] = av.y;
        As[lcol + 2][lrow] = av.z; As[lcol + 3][lrow] = av.w;
        Bs[lcol + 0][lrow] = bv.x; Bs[lcol + 1][lrow] = bv.y;
        Bs[lcol + 2][lrow] = bv.z; Bs[lcol + 3][lrow] = bv.w;
        __syncthreads();
        #pragma unroll
        for (int kk = 0; kk < 16; kk++) {
            float4 a = *(const float4*)&As[kk][ty * 4];
            float4 b = *(const float4*)&Bs[kk][tx * 4];
            acc[0][0] += a.x * b.x; acc[0][1] += a.x * b.y; acc[0][2] += a.x * b.z; acc[0][3] += a.x * b.w;
            acc[1][0] += a.y * b.x; acc[1][1] += a.y * b.y; acc[1][2] += a.y * b.z; acc[1][3] += a.y * b.w;
            acc[2][0] += a.z * b.x; acc[2][1] += a.z * b.y; acc[2][2] += a.z * b.z; acc[2][3] += a.z * b.w;
            acc[3][0] += a.w * b.x; acc[3][1] += a.w * b.y; acc[3][2] += a.w * b.z; acc[3][3] += a.w * b.w;
        }
        __syncthreads();
    }

    #pragma unroll
    for (int i = 0; i < 4; i++) {
        int m = m0 + ty * 4 + i;
        if (m >= M) continue;
        #pragma unroll
        for (int j = 0; j < 4; j++) {
            int n = n0 + tx * 4 + j;
            float c = acc[i][j] + bias[n];
            if (EPI == 1) c = 0.5f * c * (1.0f + erff(c * 0.70710678118654752f));
            if (EPI == 2) c += res[(size_t)m * N + n];
            C[(size_t)m * N + n] = c;
        }
    }
}

// ---------------- window reverse + reverse shift + residual ----------------
__global__ void merge_residual_kernel(const float* __restrict__ x,
                                      const float* __restrict__ proj,
                                      float* __restrict__ x2) {
    size_t idx = (size_t)blockIdx.x * blockDim.x + threadIdx.x;
    if (idx >= (size_t)MTOT * CC) return;
    int c = idx & (CC - 1);
    size_t t = idx >> 7;
    int b = (int)(t / LL);
    int l = (int)(t % LL);
    int i = l / WW2, j = l % WW2;
    int pi = (i + HH - SS) % HH;       // (i - 3) mod 49
    int pj = (j + WW2 - SS) % WW2;
    int w = (pi / 7) * 7 + (pj / 7);
    int n = (pi % 7) * 7 + (pj % 7);
    x2[idx] = x[idx] + proj[(((size_t)b * NWIN + w) * NTOK + n) * CC + c];
}

// ---------------- launch ----------------
extern "C" void kernel_launch(void* const* d_in, const int* in_sizes, int n_in,
                              void* d_out, int out_size) {
    const float* x      = (const float*)d_in[0];
    const float* n1w    = (const float*)d_in[1];
    const float* n1b    = (const float*)d_in[2];
    const float* qkv_w  = (const float*)d_in[3];
    const float* qkv_b  = (const float*)d_in[4];
    const float* proj_w = (const float*)d_in[5];
    const float* proj_b = (const float*)d_in[6];
    const float* rpb    = (const float*)d_in[7];
    const float* n2w    = (const float*)d_in[8];
    const float* n2b    = (const float*)d_in[9];
    const float* fc1_w  = (const float*)d_in[10];
    const float* fc1_b  = (const float*)d_in[11];
    const float* fc2_w  = (const float*)d_in[12];
    const float* fc2_b  = (const float*)d_in[13];
    float* out = (float*)d_out;

    float *xw, *qkv, *attnout, *x2, *ln2, *h1;
    cudaGetSymbolAddress((void**)&xw,      g_xw);
    cudaGetSymbolAddress((void**)&qkv,     g_qkv);
    cudaGetSymbolAddress((void**)&attnout, g_attnout);
    cudaGetSymbolAddress((void**)&x2,      g_x2);
    cudaGetSymbolAddress((void**)&ln2,     g_ln2);
    cudaGetSymbolAddress((void**)&h1,      g_h1);

    const int MT = ( MTOT + 63 ) / 64;   // 1801 m-tiles

    // 1) LN1 + shift + window partition
    ln1_shift_window_kernel<<<MTOT, 128>>>(x, n1w, n1b, xw);
    // 2) QKV GEMM: [M,384] = xw @ qkv_w^T + b
    gemm64_kernel<0><<<dim3(MT, 384 / 64), 256>>>(xw, qkv_w, qkv_b, qkv, MTOT, 384, CC, nullptr);
    // 3) fused window attention
    attn_kernel<<<dim3(BATCH * NWIN, NHEAD), 256>>>(qkv, rpb, attnout);
    // 4) proj GEMM (reuse xw buffer as proj output)
    gemm64_kernel<0><<<dim3(MT, CC / 64), 256>>>(attnout, proj_w, proj_b, xw, MTOT, CC, CC, nullptr);
    // 5) window reverse + unshift + residual
    {
        size_t total = (size_t)MTOT * CC;
        int blocks = (int)((total + 255) / 256);
        merge_residual_kernel<<<blocks, 256>>>(x, xw, x2);
    }
    // 6) LN2
    ln2_kernel<<<MTOT, 128>>>(x2, n2w, n2b, ln2);
    // 7) FC1 + exact GELU
    gemm64_kernel<1><<<dim3(MT, HID / 64), 256>>>(ln2, fc1_w, fc1_b, h1, MTOT, HID, CC, nullptr);
    // 8) FC2 + residual -> out
    gemm64_kernel<2><<<dim3(MT, CC / 64), 256>>>(h1, fc2_w, fc2_b, out, MTOT, CC, HID, x2);
}

// round 4
// speedup vs baseline: 5.7971x; 5.7971x over previous
#include <cuda_runtime.h>
#include <cuda_bf16.h>
#include <math.h>
#include <stdint.h>

// ---------------- problem constants ----------------
#define BATCH 48
#define HH 49
#define WW2 49
#define CC 128
#define LL (HH * WW2)            // 2401
#define NHEAD 4
#define HD 32
#define WS 7
#define SS 3
#define NWIN 49
#define NTOK 49
#define MTOT (BATCH * LL)        // 115248
#define HID 512

// ---------------- scratch (device globals; no allocations) ----------------
__device__ __nv_bfloat16 g_xw[(size_t)MTOT * CC];
__device__ __nv_bfloat16 g_qkvb[(size_t)MTOT * 3 * CC];
__device__ __nv_bfloat16 g_attn[(size_t)MTOT * CC];
__device__ __nv_bfloat16 g_ln2b[(size_t)MTOT * CC];
__device__ __nv_bfloat16 g_h1[(size_t)MTOT * HID];
__device__ float         g_x2[(size_t)MTOT * CC];
__device__ __nv_bfloat16 g_wqkv[384 * 128];
__device__ __nv_bfloat16 g_wproj[128 * 128];
__device__ __nv_bfloat16 g_wfc1[512 * 128];
__device__ __nv_bfloat16 g_wfc2[128 * 512];

// ================= PTX helpers (baseline sm_80+ features only) =================
__device__ __forceinline__ uint32_t smem_u32(const void* p) {
    uint32_t a;
    asm("{ .reg .u64 t; cvta.to.shared.u64 t, %1; cvt.u32.u64 %0, t; }" : "=r"(a) : "l"(p));
    return a;
}
__device__ __forceinline__ void mma_bf16(float* c, uint32_t a0, uint32_t a1, uint32_t a2,
                                         uint32_t a3, uint32_t b0, uint32_t b1) {
    asm volatile("mma.sync.aligned.m16n8k16.row.col.f32.bf16.bf16.f32 "
                 "{%0,%1,%2,%3}, {%4,%5,%6,%7}, {%8,%9}, {%0,%1,%2,%3};"
                 : "+f"(c[0]), "+f"(c[1]), "+f"(c[2]), "+f"(c[3])
                 : "r"(a0), "r"(a1), "r"(a2), "r"(a3), "r"(b0), "r"(b1));
}
__device__ __forceinline__ void ldmx4(uint32_t* r, uint32_t addr) {
    asm volatile("ldmatrix.sync.aligned.m8n8.x4.shared.b16 {%0,%1,%2,%3}, [%4];"
                 : "=r"(r[0]), "=r"(r[1]), "=r"(r[2]), "=r"(r[3]) : "r"(addr));
}
__device__ __forceinline__ void cp_async16(uint32_t dst, const void* src, int srcsize) {
    asm volatile("cp.async.cg.shared.global [%0], [%1], 16, %2;"
                 :: "r"(dst), "l"(src), "r"(srcsize) : "memory");
}
#define CP_COMMIT() asm volatile("cp.async.commit_group;" ::: "memory")
#define CP_WAIT(n)  asm volatile("cp.async.wait_group %0;" :: "n"(n) : "memory")

// ---------------- weight fp32 -> bf16 conversion ----------------
__global__ void cvt_kernel(const float* __restrict__ src, __nv_bfloat16* __restrict__ dst, int n) {
    int i = blockIdx.x * 256 + threadIdx.x;
    if (i < n) dst[i] = __float2bfloat16(src[i]);
}

// ---------------- LN1 + cyclic shift + window partition (warp per row) ----------------
__global__ void __launch_bounds__(256) ln1_kernel(const float* __restrict__ x,
                                                  const float* __restrict__ gw,
                                                  const float* __restrict__ gb,
                                                  __nv_bfloat16* __restrict__ xw) {
    int warp = threadIdx.x >> 5, lane = threadIdx.x & 31;
    int gid = blockIdx.x * 8 + warp;          // 0..MTOT-1
    int b = gid / (NWIN * NTOK);
    int r = gid % (NWIN * NTOK);
    int w = r / NTOK, n = r % NTOK;
    int i = (w / 7) * 7 + n / 7, j = (w % 7) * 7 + n % 7;
    int si = (i + SS) % HH, sj = (j + SS) % WW2;
    const float4* src = (const float4*)(x + ((size_t)b * LL + (size_t)si * WW2 + sj) * CC) + lane;
    float4 v = *src;
    float s  = v.x + v.y + v.z + v.w;
    float s2 = v.x * v.x + v.y * v.y + v.z * v.z + v.w * v.w;
    #pragma unroll
    for (int o = 16; o; o >>= 1) {
        s  += __shfl_xor_sync(0xFFFFFFFFu, s,  o);
        s2 += __shfl_xor_sync(0xFFFFFFFFu, s2, o);
    }
    float mean = s * (1.0f / CC);
    float var  = s2 * (1.0f / CC) - mean * mean;
    float rstd = rsqrtf(var + 1e-5f);
    float4 gwv = ((const float4*)gw)[lane];
    float4 gbv = ((const float4*)gb)[lane];
    float o0 = (v.x - mean) * rstd * gwv.x + gbv.x;
    float o1 = (v.y - mean) * rstd * gwv.y + gbv.y;
    float o2 = (v.z - mean) * rstd * gwv.z + gbv.z;
    float o3 = (v.w - mean) * rstd * gwv.w + gbv.w;
    __nv_bfloat162 p0 = __float22bfloat162_rn(make_float2(o0, o1));
    __nv_bfloat162 p1 = __float22bfloat162_rn(make_float2(o2, o3));
    ((uint2*)(xw + (size_t)gid * CC))[lane] = make_uint2(*(uint32_t*)&p0, *(uint32_t*)&p1);
}

// ---------------- LN2 (warp per row) ----------------
__global__ void __launch_bounds__(256) ln2_kernel(const float* __restrict__ x2,
                                                  const float* __restrict__ gw,
                                                  const float* __restrict__ gb,
                                                  __nv_bfloat16* __restrict__ out) {
    int warp = threadIdx.x >> 5, lane = threadIdx.x & 31;
    int gid = blockIdx.x * 8 + warp;
    float4 v = ((const float4*)(x2 + (size_t)gid * CC))[lane];
    float s  = v.x + v.y + v.z + v.w;
    float s2 = v.x * v.x + v.y * v.y + v.z * v.z + v.w * v.w;
    #pragma unroll
    for (int o = 16; o; o >>= 1) {
        s  += __shfl_xor_sync(0xFFFFFFFFu, s,  o);
        s2 += __shfl_xor_sync(0xFFFFFFFFu, s2, o);
    }
    float mean = s * (1.0f / CC);
    float var  = s2 * (1.0f / CC) - mean * mean;
    float rstd = rsqrtf(var + 1e-5f);
    float4 gwv = ((const float4*)gw)[lane];
    float4 gbv = ((const float4*)gb)[lane];
    float o0 = (v.x - mean) * rstd * gwv.x + gbv.x;
    float o1 = (v.y - mean) * rstd * gwv.y + gbv.y;
    float o2 = (v.z - mean) * rstd * gwv.z + gbv.z;
    float o3 = (v.w - mean) * rstd * gwv.w + gbv.w;
    __nv_bfloat162 p0 = __float22bfloat162_rn(make_float2(o0, o1));
    __nv_bfloat162 p1 = __float22bfloat162_rn(make_float2(o2, o3));
    ((uint2*)(out + (size_t)gid * CC))[lane] = make_uint2(*(uint32_t*)&p0, *(uint32_t*)&p1);
}

// ---------------- fused window attention (bf16 I/O, fp32 math) ----------------
__device__ __forceinline__ int region1d(int p) {
    return (p < HH - WS) ? 0 : ((p < HH - SS) ? 1 : 2);
}

__global__ void __launch_bounds__(256) attn_kernel(const __nv_bfloat16* __restrict__ qkv,
                                                   const float* __restrict__ rpb,
                                                   __nv_bfloat16* __restrict__ out) {
    int bw = blockIdx.x;
    int h  = blockIdx.y;
    int w  = bw % NWIN;

    __shared__ float sq[NTOK * HD];
    __shared__ float skT[HD * NTOK];
    __shared__ float sv[NTOK * HD];
    __shared__ float ss[NTOK * NTOK];

    int tid = threadIdx.x;
    const float scale = 0.17677669529663687f;
    size_t base = (size_t)bw * NTOK * (3 * CC);

    for (int i = tid; i < NTOK * HD; i += 256) {
        int n = i >> 5, d = i & 31;
        const __nv_bfloat16* row = qkv + base + (size_t)n * (3 * CC) + h * HD + d;
        sq[i] = __bfloat162float(row[0]) * scale;
        skT[d * NTOK + n] = __bfloat162float(row[CC]);
        sv[i] = __bfloat162float(row[2 * CC]);
    }
    __syncthreads();

    int wh = w / 7, wwc = w % 7;
    for (int idx = tid; idx < NTOK * NTOK; idx += 256) {
        int n = idx / NTOK, m = idx % NTOK;
        float acc = 0.f;
        #pragma unroll
        for (int d = 0; d < HD; d++) acc += sq[n * HD + d] * skT[d * NTOK + m];
        int ni = n / 7, nj = n % 7, mi = m / 7, mj = m % 7;
        int rel = (ni - mi + WS - 1) * (2 * WS - 1) + (nj - mj + WS - 1);
        acc += rpb[rel * NHEAD + h];
        int h1 = wh * 7 + mi, w1 = wwc * 7 + mj;
        int h2 = ni * 7 + mi, w2 = nj * 7 + mj;
        int r1 = 3 * region1d(h1) + region1d(w1);
        int r2 = 3 * region1d(h2) + region1d(w2);
        if (r1 != r2) acc -= 100.0f;
        ss[idx] = acc;
    }
    __syncthreads();

    int warp = tid >> 5, lane = tid & 31;
    for (int n = warp; n < NTOK; n += 8) {
        float v0 = ss[n * NTOK + lane];
        float v1 = (lane + 32 < NTOK) ? ss[n * NTOK + lane + 32] : -1e30f;
        float mx = fmaxf(v0, v1);
        #pragma unroll
        for (int o = 16; o; o >>= 1) mx = fmaxf(mx, __shfl_xor_sync(0xFFFFFFFFu, mx, o));
        float e0 = __expf(v0 - mx);
        float e1 = (lane + 32 < NTOK) ? __expf(v1 - mx) : 0.f;
        float sum = e0 + e1;
        #pragma unroll
        for (int o = 16; o; o >>= 1) sum += __shfl_xor_sync(0xFFFFFFFFu, sum, o);
        float inv = 1.0f / sum;
        ss[n * NTOK + lane] = e0 * inv;
        if (lane + 32 < NTOK) ss[n * NTOK + lane + 32] = e1 * inv;
    }
    __syncthreads();

    for (int i = tid; i < NTOK * (HD / 2); i += 256) {
        int n = i >> 4, d2 = (i & 15) * 2;
        float a0 = 0.f, a1 = 0.f;
        #pragma unroll
        for (int m = 0; m < NTOK; m++) {
            float p = ss[n * NTOK + m];
            a0 += p * sv[m * HD + d2];
            a1 += p * sv[m * HD + d2 + 1];
        }
        __nv_bfloat162 pk = __float22bfloat162_rn(make_float2(a0, a1));
        *(__nv_bfloat162*)(out + ((size_t)bw * NTOK + n) * CC + h * HD + d2) = pk;
    }
}

// ---------------- bf16 HMMA GEMM: C[M,N] = A[M,K] @ W[N,K]^T + bias ----------------
// CTA 128x128, 8 warps (2x4), warp tile 64x32, K chunks of 64, double-buffered cp.async.
// EPI: 0 = bf16 out, 1 = bf16 out + exact GELU, 2 = fp32 out + residual add
#define GSMEM 65536

template <int EPI>
__global__ void __launch_bounds__(256) gemm_mma(
    const __nv_bfloat16* __restrict__ A, const __nv_bfloat16* __restrict__ W,
    const float* __restrict__ bias, void* __restrict__ Cout,
    int M, int N, int K, const float* __restrict__ res)
{
    extern __shared__ char smem[];
    uint32_t sb = smem_u32(smem);
    const int tid = threadIdx.x, warp = tid >> 5, lane = tid & 31;
    const int wm = warp >> 2, wn = warp & 3;
    const int m0 = blockIdx.x * 128, n0 = blockIdx.y * 128;
    const uint32_t sA[2] = {sb, sb + 16384u};
    const uint32_t sB[2] = {sb + 32768u, sb + 49152u};
    const int nch = K >> 6;

    const int lrow = tid >> 3;        // 0..31
    const int lck  = tid & 7;         // 16B chunk within 128B row

    float acc[4][4][4];
    #pragma unroll
    for (int a = 0; a < 4; a++)
        #pragma unroll
        for (int b = 0; b < 4; b++)
            #pragma unroll
            for (int c = 0; c < 4; c++) acc[a][b][c] = 0.f;

    // frag lane address components
    const int idx = lane >> 3, l8 = lane & 7;
    const int a_rowb = wm * 64 + (idx & 1) * 8 + l8;
    const int a_kb   = (idx >> 1) * 16;
    const int b_rowb = wn * 32 + (idx >> 1) * 8 + l8;
    const int b_kb   = (idx & 1) * 16;
    const uint32_t swz = (uint32_t)(l8 << 4);

    // ---- chunk loader ----
    auto load_chunk = [&](int ch) {
        int buf = ch & 1, k0 = ch << 6;
        const __nv_bfloat16* Ag = A + (size_t)m0 * K + k0;
        #pragma unroll
        for (int it = 0; it < 4; it++) {
            int row = lrow + it * 32;
            int sz = (m0 + row < M) ? 16 : 0;
            uint32_t dst = sA[buf] + row * 128 + ((lck * 16) ^ ((row & 7) << 4));
            cp_async16(dst, Ag + (size_t)row * K + lck * 8, sz);
        }
        const __nv_bfloat16* Wg = W + (size_t)n0 * K + k0;
        #pragma unroll
        for (int it = 0; it < 4; it++) {
            int row = lrow + it * 32;
            uint32_t dst = sB[buf] + row * 128 + ((lck * 16) ^ ((row & 7) << 4));
            cp_async16(dst, Wg + (size_t)row * K + lck * 8, 16);
        }
        CP_COMMIT();
    };

    load_chunk(0);

    for (int ch = 0; ch < nch; ch++) {
        if (ch + 1 < nch) { load_chunk(ch + 1); CP_WAIT(1); }
        else              { CP_WAIT(0); }
        __syncthreads();
        int buf = ch & 1;
        uint32_t Abase = sA[buf] + a_rowb * 128;
        uint32_t Bbase = sB[buf] + b_rowb * 128;
        #pragma unroll
        for (int ks = 0; ks < 4; ks++) {
            uint32_t af[4][4], bg[2][4];
            #pragma unroll
            for (int mt = 0; mt < 4; mt++)
                ldmx4(af[mt], Abase + mt * 16 * 128 + (((uint32_t)(ks * 32 + a_kb)) ^ swz));
            #pragma unroll
            for (int np = 0; np < 2; np++)
                ldmx4(bg[np], Bbase + np * 16 * 128 + (((uint32_t)(ks * 32 + b_kb)) ^ swz));
            #pragma unroll
            for (int mt = 0; mt < 4; mt++)
                #pragma unroll
                for (int nt = 0; nt < 4; nt++)
                    mma_bf16(acc[mt][nt],
                             af[mt][0], af[mt][1], af[mt][2], af[mt][3],
                             bg[nt >> 1][(nt & 1) * 2], bg[nt >> 1][(nt & 1) * 2 + 1]);
        }
        __syncthreads();
    }

    // ---- epilogue (register -> gmem) ----
    const int erow = m0 + wm * 64 + (lane >> 2);
    const int ecol = n0 + wn * 32 + (lane & 3) * 2;
    #pragma unroll
    for (int mt = 0; mt < 4; mt++) {
        #pragma unroll
        for (int nt = 0; nt < 4; nt++) {
            int row = erow + mt * 16;
            int col = ecol + nt * 8;
            float b0 = bias[col], b1 = bias[col + 1];
            float v0 = acc[mt][nt][0] + b0, v1 = acc[mt][nt][1] + b1;
            float v2 = acc[mt][nt][2] + b0, v3 = acc[mt][nt][3] + b1;
            if (EPI == 1) {
                v0 = 0.5f * v0 * (1.0f + erff(v0 * 0.70710678118654752f));
                v1 = 0.5f * v1 * (1.0f + erff(v1 * 0.70710678118654752f));
                v2 = 0.5f * v2 * (1.0f + erff(v2 * 0.70710678118654752f));
                v3 = 0.5f * v3 * (1.0f + erff(v3 * 0.70710678118654752f));
            }
            if (EPI == 2) {
                float* C = (float*)Cout;
                if (row < M) {
                    float2 rr = *(const float2*)(res + (size_t)row * N + col);
                    *(float2*)(C + (size_t)row * N + col) = make_float2(v0 + rr.x, v1 + rr.y);
                }
                if (row + 8 < M) {
                    float2 rr = *(const float2*)(res + (size_t)(row + 8) * N + col);
                    *(float2*)(C + (size_t)(row + 8) * N + col) = make_float2(v2 + rr.x, v3 + rr.y);
                }
            } else {
                __nv_bfloat16* C = (__nv_bfloat16*)Cout;
                if (row < M) {
                    __nv_bfloat162 p = __float22bfloat162_rn(make_float2(v0, v1));
                    *(__nv_bfloat162*)(C + (size_t)row * N + col) = p;
                }
                if (row + 8 < M) {
                    __nv_bfloat162 p = __float22bfloat162_rn(make_float2(v2, v3));
                    *(__nv_bfloat162*)(C + (size_t)(row + 8) * N + col) = p;
                }
            }
        }
    }
}

// ---------------- window reverse + reverse shift + residual (x4 vectorized) ----------------
__global__ void __launch_bounds__(256) merge_kernel(const float* __restrict__ x,
                                                    const __nv_bfloat16* __restrict__ proj,
                                                    float* __restrict__ x2) {
    int idx4 = blockIdx.x * 256 + threadIdx.x;     // < MTOT*32
    int t = idx4 >> 5;
    int c4 = (idx4 & 31) * 4;
    int b = t / LL, l = t % LL;
    int i = l / WW2, j = l % WW2;
    int pi = (i + HH - SS) % HH;
    int pj = (j + WW2 - SS) % WW2;
    int w = (pi / 7) * 7 + (pj / 7);
    int n = (pi % 7) * 7 + (pj % 7);
    float4 xv = *(const float4*)(x + (size_t)idx4 * 4);
    uint2 pv = *(const uint2*)(proj + (((size_t)b * NWIN + w) * NTOK + n) * CC + c4);
    __nv_bfloat162 p0 = *(__nv_bfloat162*)&pv.x;
    __nv_bfloat162 p1 = *(__nv_bfloat162*)&pv.y;
    float4 o = make_float4(xv.x + __bfloat162float(p0.x), xv.y + __bfloat162float(p0.y),
                           xv.z + __bfloat162float(p1.x), xv.w + __bfloat162float(p1.y));
    *(float4*)(x2 + (size_t)idx4 * 4) = o;
}

// ---------------- launch ----------------
extern "C" void kernel_launch(void* const* d_in, const int* in_sizes, int n_in,
                              void* d_out, int out_size) {
    const float* x      = (const float*)d_in[0];
    const float* n1w    = (const float*)d_in[1];
    const float* n1b    = (const float*)d_in[2];
    const float* qkv_w  = (const float*)d_in[3];
    const float* qkv_b  = (const float*)d_in[4];
    const float* proj_w = (const float*)d_in[5];
    const float* proj_b = (const float*)d_in[6];
    const float* rpb    = (const float*)d_in[7];
    const float* n2w    = (const float*)d_in[8];
    const float* n2b    = (const float*)d_in[9];
    const float* fc1_w  = (const float*)d_in[10];
    const float* fc1_b  = (const float*)d_in[11];
    const float* fc2_w  = (const float*)d_in[12];
    const float* fc2_b  = (const float*)d_in[13];
    float* out = (float*)d_out;

    __nv_bfloat16 *xw, *qkvb, *attn, *ln2b, *h1, *wqkv, *wproj, *wfc1, *wfc2;
    float* x2;
    cudaGetSymbolAddress((void**)&xw,    g_xw);
    cudaGetSymbolAddress((void**)&qkvb,  g_qkvb);
    cudaGetSymbolAddress((void**)&attn,  g_attn);
    cudaGetSymbolAddress((void**)&ln2b,  g_ln2b);
    cudaGetSymbolAddress((void**)&h1,    g_h1);
    cudaGetSymbolAddress((void**)&x2,    g_x2);
    cudaGetSymbolAddress((void**)&wqkv,  g_wqkv);
    cudaGetSymbolAddress((void**)&wproj, g_wproj);
    cudaGetSymbolAddress((void**)&wfc1,  g_wfc1);
    cudaGetSymbolAddress((void**)&wfc2,  g_wfc2);

    cudaFuncSetAttribute(gemm_mma<0>, cudaFuncAttributeMaxDynamicSharedMemorySize, GSMEM);
    cudaFuncSetAttribute(gemm_mma<1>, cudaFuncAttributeMaxDynamicSharedMemorySize, GSMEM);
    cudaFuncSetAttribute(gemm_mma<2>, cudaFuncAttributeMaxDynamicSharedMemorySize, GSMEM);

    const int MT = (MTOT + 127) / 128;   // 901

    // 0) convert weights fp32 -> bf16 (constant work, ~200k elems)
    cvt_kernel<<<(384 * 128 + 255) / 256, 256>>>(qkv_w,  wqkv,  384 * 128);
    cvt_kernel<<<(128 * 128 + 255) / 256, 256>>>(proj_w, wproj, 128 * 128);
    cvt_kernel<<<(512 * 128 + 255) / 256, 256>>>(fc1_w,  wfc1,  512 * 128);
    cvt_kernel<<<(128 * 512 + 255) / 256, 256>>>(fc2_w,  wfc2,  128 * 512);

    // 1) LN1 + shift + window partition -> bf16
    ln1_kernel<<<MTOT / 8, 256>>>(x, n1w, n1b, xw);
    // 2) QKV GEMM (bf16 in/out)
    gemm_mma<0><<<dim3(MT, 3), 256, GSMEM>>>(xw, wqkv, qkv_b, qkvb, MTOT, 384, CC, nullptr);
    // 3) fused window attention
    attn_kernel<<<dim3(BATCH * NWIN, NHEAD), 256>>>(qkvb, rpb, attn);
    // 4) proj GEMM (reuse xw as bf16 output)
    gemm_mma<0><<<dim3(MT, 1), 256, GSMEM>>>(attn, wproj, proj_b, xw, MTOT, CC, CC, nullptr);
    // 5) window reverse + unshift + residual -> fp32 x2
    merge_kernel<<<MTOT * 32 / 256, 256>>>(x, xw, x2);
    // 6) LN2 -> bf16
    ln2_kernel<<<MTOT / 8, 256>>>(x2, n2w, n2b, ln2b);
    // 7) FC1 + exact GELU -> bf16
    gemm_mma<1><<<dim3(MT, 4), 256, GSMEM>>>(ln2b, wfc1, fc1_b, h1, MTOT, HID, CC, nullptr);
    // 8) FC2 + residual -> fp32 out
    gemm_mma<2><<<dim3(MT, 1), 256, GSMEM>>>(h1, wfc2, fc2_b, out, MTOT, CC, HID, x2);
}